// round 8
// baseline (speedup 1.0000x reference)
#include <cuda_runtime.h>
#include <cuda_bf16.h>
#include <cuda_fp16.h>

#define BB   4
#define CC   256
#define CHH  128
#define NN   4096

#define TILE   128
#define BK     16
#define SPITCH 132   // 128 + 4 pad

// ---------------- scratch ----------------
__device__ float    g_gv   [(size_t)BB * NN * CHH];   // g fp32 (k1 out, k3z in)
__device__ __half   g_gvh  [(size_t)BB * NN * CHH];   // g/Z fp16 (k3z out, k4 in)
__device__ float    g_O    [(size_t)BB * NN * CHH];   // [b][i][ch]
__device__ __half   g_P    [(size_t)BB * NN * NN];    // probs fp16 [b][j][i]
__device__ unsigned g_rowmax[BB * NN];
__device__ float    g_Zpart[(size_t)BB * NN * 32];    // per-(row, i-tile) partial sums
// split-bf16 theta/phi (big + residual)
__device__ __nv_bfloat16 g_thB[(size_t)BB * NN * CHH];
__device__ __nv_bfloat16 g_thS[(size_t)BB * NN * CHH];
__device__ __nv_bfloat16 g_phB[(size_t)BB * NN * CHH];
__device__ __nv_bfloat16 g_phS[(size_t)BB * NN * CHH];
// split-bf16 x (A operand for k1) and transposed weights (B operand for k1)
__device__ __nv_bfloat16 g_xB [(size_t)BB * CC * NN];
__device__ __nv_bfloat16 g_xS [(size_t)BB * CC * NN];
__device__ __nv_bfloat16 g_wTB[3 * CC * CHH];          // [proj][c][o]
__device__ __nv_bfloat16 g_wTS[3 * CC * CHH];

// ---------------- fast exp (FFMA-only, x <= ~0) ----------------
__device__ __forceinline__ float fast_exp(float x) {
    float t = fmaxf(x * 1.4426950408889634f, -120.0f);
    float z = t + 12582912.0f;
    int   e = __float_as_int(z);
    float f = t - (z - 12582912.0f);
    float p = 1.3333558e-3f;
    p = fmaf(p, f, 9.6181291e-3f);
    p = fmaf(p, f, 5.5504109e-2f);
    p = fmaf(p, f, 2.4022651e-1f);
    p = fmaf(p, f, 6.9314718e-1f);
    p = fmaf(p, f, 1.0f);
    return __int_as_float((e << 23) + __float_as_int(p));
}

// ---------------- monotonic float<->uint for atomicMax ----------------
__device__ __forceinline__ unsigned enc_f(float v) {
    unsigned b = __float_as_uint(v);
    return (b & 0x80000000u) ? ~b : (b | 0x80000000u);
}
__device__ __forceinline__ float dec_f(unsigned u) {
    return (u & 0x80000000u) ? __uint_as_float(u & 0x7fffffffu)
                             : __uint_as_float(~u);
}

// ---------------- tensor-core helpers ----------------
__device__ __forceinline__ void mma_bf16(float* d, const unsigned* a, const unsigned* b) {
    asm volatile("mma.sync.aligned.m16n8k16.row.col.f32.bf16.bf16.f32 "
                 "{%0,%1,%2,%3}, {%4,%5,%6,%7}, {%8,%9}, {%0,%1,%2,%3};"
                 : "+f"(d[0]), "+f"(d[1]), "+f"(d[2]), "+f"(d[3])
                 : "r"(a[0]), "r"(a[1]), "r"(a[2]), "r"(a[3]),
                   "r"(b[0]), "r"(b[1]));
}
__device__ __forceinline__ void mma_fp16(float* d, const unsigned* a, const unsigned* b) {
    asm volatile("mma.sync.aligned.m16n8k16.row.col.f32.f16.f16.f32 "
                 "{%0,%1,%2,%3}, {%4,%5,%6,%7}, {%8,%9}, {%0,%1,%2,%3};"
                 : "+f"(d[0]), "+f"(d[1]), "+f"(d[2]), "+f"(d[3])
                 : "r"(a[0]), "r"(a[1]), "r"(a[2]), "r"(a[3]),
                   "r"(b[0]), "r"(b[1]));
}
__device__ __forceinline__ void ldsm4t(unsigned* r, const void* smem) {
    unsigned a = (unsigned)__cvta_generic_to_shared(smem);
    asm volatile("ldmatrix.sync.aligned.m8n8.x4.trans.shared.b16 {%0,%1,%2,%3}, [%4];"
                 : "=r"(r[0]), "=r"(r[1]), "=r"(r[2]), "=r"(r[3]) : "r"(a));
}
__device__ __forceinline__ void ldsm4(unsigned* r, const void* smem) {
    unsigned a = (unsigned)__cvta_generic_to_shared(smem);
    asm volatile("ldmatrix.sync.aligned.m8n8.x4.shared.b16 {%0,%1,%2,%3}, [%4];"
                 : "=r"(r[0]), "=r"(r[1]), "=r"(r[2]), "=r"(r[3]) : "r"(a));
}
__device__ __forceinline__ void cp16(void* smem, const void* g) {
    unsigned a = (unsigned)__cvta_generic_to_shared(smem);
    asm volatile("cp.async.cg.shared.global [%0], [%1], 16;" :: "r"(a), "l"(g));
}
// split a float2 into packed bf16x2 (big) + packed bf16x2 (residual)
__device__ __forceinline__ void split2(float v0, float v1, unsigned& big, unsigned& sml) {
    asm("cvt.rn.bf16x2.f32 %0, %1, %2;" : "=r"(big) : "f"(v1), "f"(v0));
    float b0 = __uint_as_float(big << 16);
    float b1 = __uint_as_float(big & 0xffff0000u);
    float r0 = v0 - b0, r1 = v1 - b1;
    asm("cvt.rn.bf16x2.f32 %0, %1, %2;" : "=r"(sml) : "f"(r1), "f"(r0));
}

// ================= K0: init rowmax =================
__global__ __launch_bounds__(256) void k0_init() {
    g_rowmax[blockIdx.x * 256 + threadIdx.x] = 0u;
}

// ================= K0x: split x -> bf16 big/small planes =================
__global__ __launch_bounds__(256) void k0x_split(const float* __restrict__ x) {
    size_t i4 = (size_t)blockIdx.x * 256 + threadIdx.x;
    float4 v = ((const float4*)x)[i4];
    unsigned b0, s0, b1, s1;
    split2(v.x, v.y, b0, s0);
    split2(v.z, v.w, b1, s1);
    ((uint2*)g_xB)[i4] = make_uint2(b0, b1);
    ((uint2*)g_xS)[i4] = make_uint2(s0, s1);
}

// ================= K0w: transpose + split weights -> [proj][c][o] =================
__global__ __launch_bounds__(256) void k0w_split(
    const float* __restrict__ tw, const float* __restrict__ pw,
    const float* __restrict__ gw) {
    int idx = blockIdx.x * 256 + threadIdx.x;
    int o = idx & 127;
    int c = (idx >> 7) & 255;
    int p = idx >> 15;
    const float* w = p == 0 ? tw : (p == 1 ? pw : gw);
    float v = w[o * CC + c];
    __nv_bfloat16 big = __float2bfloat16(v);
    __nv_bfloat16 sml = __float2bfloat16(v - __bfloat162float(big));
    g_wTB[idx] = big;
    g_wTS[idx] = sml;
}

// ================= K1: projections via split-bf16 x3 mma =================
#define K1_PA 72
#define K1_PB 136
__global__ __launch_bounds__(256) void k1_mma(
    const float* __restrict__ tb, const float* __restrict__ pb,
    const float* __restrict__ gb)
{
    __shared__ __align__(16) __nv_bfloat16 As[3][2][BK * K1_PA];
    __shared__ __align__(16) __nv_bfloat16 Bs[3][2][BK * K1_PB];
    const int b    = blockIdx.z;
    const int proj = blockIdx.y;
    const int i0   = blockIdx.x * 64;
    const int tid  = threadIdx.x;
    const int warp = tid >> 5, lane = tid & 31;
    const int g = lane >> 2, t = lane & 3;
    const int wm = (warp >> 2) * 32;
    const int wn = (warp & 3) * 32;

    const __nv_bfloat16* xB = g_xB + (size_t)b * CC * NN;
    const __nv_bfloat16* xS = g_xS + (size_t)b * CC * NN;
    const __nv_bfloat16* wB = g_wTB + (size_t)proj * CC * CHH;
    const __nv_bfloat16* wS = g_wTS + (size_t)proj * CC * CHH;
    const float* bias = proj == 0 ? tb : (proj == 1 ? pb : gb);

    const int krA = (lane & 7) + ((lane & 16) ? 8 : 0);
    const int mcA = (lane & 8) ? 8 : 0;
    const int krB = (lane & 7) + ((lane & 8) ? 8 : 0);
    const int ncB = (lane & 16) ? 8 : 0;

    const int av  = tid >> 7, ac = tid & 127;
    const int ar  = ac >> 3, acol = (ac & 7) * 8;
    float acc[2][4][4] = {};

#define K1_LOAD(st, k0)                                                              \
    {                                                                                \
        const __nv_bfloat16* xa = av ? xS : xB;                                      \
        cp16(&As[st][av][ar * K1_PA + acol],                                         \
             xa + (size_t)((k0) + ar) * NN + i0 + acol);                             \
        _Pragma("unroll")                                                            \
        for (int q = 0; q < 2; ++q) {                                                \
            int idx = tid + q * 256;                                                 \
            int bv = idx >> 8, cc = idx & 255;                                       \
            int br = cc >> 4, bcol = (cc & 15) * 8;                                  \
            const __nv_bfloat16* wa = bv ? wS : wB;                                  \
            cp16(&Bs[st][bv][br * K1_PB + bcol],                                     \
                 wa + (size_t)((k0) + br) * CHH + bcol);                             \
        }                                                                            \
    }

    K1_LOAD(0, 0);
    asm volatile("cp.async.commit_group;");
    K1_LOAD(1, BK);
    asm volatile("cp.async.commit_group;");

    int s = 0;
#pragma unroll 1
    for (int it = 0; it < CC / BK; ++it) {
        asm volatile("cp.async.wait_group 1;");
        __syncthreads();

        if (it + 2 < CC / BK) {
            int st = s + 2; if (st >= 3) st -= 3;
            K1_LOAD(st, (it + 2) * BK);
        }
        asm volatile("cp.async.commit_group;");

        unsigned aB[2][4], aS[2][4], bB[2][4], bS[2][4];
#pragma unroll
        for (int mi = 0; mi < 2; ++mi) {
            ldsm4t(aB[mi], &As[s][0][krA * K1_PA + wm + mi * 16 + mcA]);
            ldsm4t(aS[mi], &As[s][1][krA * K1_PA + wm + mi * 16 + mcA]);
        }
#pragma unroll
        for (int nb = 0; nb < 2; ++nb) {
            ldsm4t(bB[nb], &Bs[s][0][krB * K1_PB + wn + nb * 16 + ncB]);
            ldsm4t(bS[nb], &Bs[s][1][krB * K1_PB + wn + nb * 16 + ncB]);
        }
#pragma unroll
        for (int mi = 0; mi < 2; ++mi)
#pragma unroll
            for (int ni = 0; ni < 4; ++ni) {
                mma_bf16(acc[mi][ni], aB[mi], &bS[ni >> 1][(ni & 1) * 2]);
                mma_bf16(acc[mi][ni], aS[mi], &bB[ni >> 1][(ni & 1) * 2]);
                mma_bf16(acc[mi][ni], aB[mi], &bB[ni >> 1][(ni & 1) * 2]);
            }
        __syncthreads();
        if (++s == 3) s = 0;
    }

    if (proj < 2) {
        __nv_bfloat16* outB = proj == 0 ? g_thB : g_phB;
        __nv_bfloat16* outS = proj == 0 ? g_thS : g_phS;
        size_t base = (size_t)b * NN * CHH;
#pragma unroll
        for (int mi = 0; mi < 2; ++mi) {
            int i = i0 + wm + mi * 16 + g;
#pragma unroll
            for (int ni = 0; ni < 4; ++ni) {
                int o = wn + ni * 8 + t * 2;
                float b0 = bias[o], b1 = bias[o + 1];
                unsigned pbv, psv;
                split2(acc[mi][ni][0] + b0, acc[mi][ni][1] + b1, pbv, psv);
                *(unsigned*)&outB[base + (size_t)i * CHH + o] = pbv;
                *(unsigned*)&outS[base + (size_t)i * CHH + o] = psv;
                split2(acc[mi][ni][2] + b0, acc[mi][ni][3] + b1, pbv, psv);
                *(unsigned*)&outB[base + (size_t)(i + 8) * CHH + o] = pbv;
                *(unsigned*)&outS[base + (size_t)(i + 8) * CHH + o] = psv;
            }
        }
    } else {
        float* ob = g_gv + (size_t)b * NN * CHH;
#pragma unroll
        for (int mi = 0; mi < 2; ++mi) {
            int i = i0 + wm + mi * 16 + g;
#pragma unroll
            for (int ni = 0; ni < 4; ++ni) {
                int o = wn + ni * 8 + t * 2;
                float b0 = bias[o], b1 = bias[o + 1];
                *(float2*)&ob[(size_t)i * CHH + o] =
                    make_float2(acc[mi][ni][0] + b0, acc[mi][ni][1] + b1);
                *(float2*)&ob[(size_t)(i + 8) * CHH + o] =
                    make_float2(acc[mi][ni][2] + b0, acc[mi][ni][3] + b1);
            }
        }
    }
}

// ================= K2a: approx rowmax of theta.phi^T (1-pass bf16, no store) ======
#define K2P 24
__global__ __launch_bounds__(256) void k2a_rowmax()
{
    __shared__ __align__(16) __nv_bfloat16 sm[2][2][128 * K2P];   // thB, phB
    const int b  = blockIdx.z;
    const int j0 = blockIdx.y * 128;
    const int i0 = blockIdx.x * 128;
    const int tid = threadIdx.x;
    const int warp = tid >> 5, lane = tid & 31;
    const int g = lane >> 2, t = lane & 3;
    const int wm = (warp >> 2) * 64;
    const int wn = (warp & 3) * 32;
    const __nv_bfloat16* thB = g_thB + (size_t)b * NN * CHH + (size_t)j0 * CHH;
    const __nv_bfloat16* phB = g_phB + (size_t)b * NN * CHH + (size_t)i0 * CHH;

    const int arow = (lane & 7) + ((lane & 8) ? 8 : 0);
    const int akof = (lane & 16) ? 8 : 0;
    const int brow = (lane & 7) + ((lane & 16) ? 8 : 0);
    const int bkof = (lane & 8) ? 8 : 0;

    float acc[4][4][4] = {};

    const int lrow = tid >> 1, lkc = (tid & 1) * 8;
#define K2A_LOAD(st, k0)                                                        \
    {                                                                           \
        cp16(&sm[st][0][lrow * K2P + lkc], thB + (size_t)lrow * CHH + (k0) + lkc); \
        cp16(&sm[st][1][lrow * K2P + lkc], phB + (size_t)lrow * CHH + (k0) + lkc); \
    }

    K2A_LOAD(0, 0);
    asm volatile("cp.async.commit_group;");

#pragma unroll 1
    for (int it = 0; it < CHH / BK; ++it) {
        const int s = it & 1;
        if (it + 1 < CHH / BK) K2A_LOAD(s ^ 1, (it + 1) * BK);
        asm volatile("cp.async.commit_group;");
        asm volatile("cp.async.wait_group 1;");
        __syncthreads();

        unsigned aB[4][4], bB[2][4];
#pragma unroll
        for (int mi = 0; mi < 4; ++mi)
            ldsm4(aB[mi], &sm[s][0][(wm + mi * 16 + arow) * K2P + akof]);
#pragma unroll
        for (int nb = 0; nb < 2; ++nb)
            ldsm4(bB[nb], &sm[s][1][(wn + nb * 16 + brow) * K2P + bkof]);
#pragma unroll
        for (int mi = 0; mi < 4; ++mi)
#pragma unroll
            for (int ni = 0; ni < 4; ++ni)
                mma_bf16(acc[mi][ni], aB[mi], &bB[ni >> 1][(ni & 1) * 2]);
        __syncthreads();
    }

#pragma unroll
    for (int mi = 0; mi < 4; ++mi) {
        int j = j0 + wm + mi * 16 + g;
        float r0 = -3.0e38f, r1 = -3.0e38f;
#pragma unroll
        for (int ni = 0; ni < 4; ++ni) {
            r0 = fmaxf(r0, fmaxf(acc[mi][ni][0], acc[mi][ni][1]));
            r1 = fmaxf(r1, fmaxf(acc[mi][ni][2], acc[mi][ni][3]));
        }
        r0 = fmaxf(r0, __shfl_xor_sync(0xffffffffu, r0, 1));
        r0 = fmaxf(r0, __shfl_xor_sync(0xffffffffu, r0, 2));
        r1 = fmaxf(r1, __shfl_xor_sync(0xffffffffu, r1, 1));
        r1 = fmaxf(r1, __shfl_xor_sync(0xffffffffu, r1, 2));
        if (t == 0) {
            atomicMax(&g_rowmax[b * NN + j],     enc_f(r0));
            atomicMax(&g_rowmax[b * NN + j + 8], enc_f(r1));
        }
    }
}

// ================= K2b: split-bf16 x3 scores -> exp -> P fp16 + Z partials =======
__global__ __launch_bounds__(256) void k2b_scores_exp()
{
    __shared__ __align__(16) __nv_bfloat16 sm[2][4][128 * K2P];
    __shared__ float spart[128][4];
    const int b  = blockIdx.z;
    const int j0 = blockIdx.y * 128;
    const int i0 = blockIdx.x * 128;
    const int tid = threadIdx.x;
    const int warp = tid >> 5, lane = tid & 31;
    const int g = lane >> 2, t = lane & 3;
    const int wm = (warp >> 2) * 64;
    const int wn = (warp & 3) * 32;
    const size_t baseJ = (size_t)b * NN * CHH + (size_t)j0 * CHH;
    const size_t baseI = (size_t)b * NN * CHH + (size_t)i0 * CHH;
    const __nv_bfloat16* thB = g_thB + baseJ;
    const __nv_bfloat16* thS = g_thS + baseJ;
    const __nv_bfloat16* phB = g_phB + baseI;
    const __nv_bfloat16* phS = g_phS + baseI;

    const int arow = (lane & 7) + ((lane & 8) ? 8 : 0);
    const int akof = (lane & 16) ? 8 : 0;
    const int brow = (lane & 7) + ((lane & 16) ? 8 : 0);
    const int bkof = (lane & 8) ? 8 : 0;

    float acc[4][4][4] = {};

    const int lrow = tid >> 1, lkc = (tid & 1) * 8;
#define K2_LOAD(st, k0)                                                        \
    {                                                                          \
        cp16(&sm[st][0][lrow * K2P + lkc], thB + (size_t)lrow * CHH + (k0) + lkc); \
        cp16(&sm[st][1][lrow * K2P + lkc], thS + (size_t)lrow * CHH + (k0) + lkc); \
        cp16(&sm[st][2][lrow * K2P + lkc], phB + (size_t)lrow * CHH + (k0) + lkc); \
        cp16(&sm[st][3][lrow * K2P + lkc], phS + (size_t)lrow * CHH + (k0) + lkc); \
    }

    K2_LOAD(0, 0);
    asm volatile("cp.async.commit_group;");

#pragma unroll 1
    for (int it = 0; it < CHH / BK; ++it) {
        const int s = it & 1;
        if (it + 1 < CHH / BK) K2_LOAD(s ^ 1, (it + 1) * BK);
        asm volatile("cp.async.commit_group;");
        asm volatile("cp.async.wait_group 1;");
        __syncthreads();

        const __nv_bfloat16* AB = sm[s][0];
        const __nv_bfloat16* AS = sm[s][1];
        const __nv_bfloat16* PB = sm[s][2];
        const __nv_bfloat16* PS = sm[s][3];

        unsigned aB[4][4], aS[4][4], bB[2][4], bS[2][4];
#pragma unroll
        for (int mi = 0; mi < 4; ++mi) {
            ldsm4(aB[mi], &AB[(wm + mi * 16 + arow) * K2P + akof]);
            ldsm4(aS[mi], &AS[(wm + mi * 16 + arow) * K2P + akof]);
        }
#pragma unroll
        for (int nb = 0; nb < 2; ++nb) {
            ldsm4(bB[nb], &PB[(wn + nb * 16 + brow) * K2P + bkof]);
            ldsm4(bS[nb], &PS[(wn + nb * 16 + brow) * K2P + bkof]);
        }
#pragma unroll
        for (int mi = 0; mi < 4; ++mi)
#pragma unroll
            for (int ni = 0; ni < 4; ++ni) {
                mma_bf16(acc[mi][ni], aB[mi], &bS[ni >> 1][(ni & 1) * 2]);
                mma_bf16(acc[mi][ni], aS[mi], &bB[ni >> 1][(ni & 1) * 2]);
                mma_bf16(acc[mi][ni], aB[mi], &bB[ni >> 1][(ni & 1) * 2]);
            }
        __syncthreads();
    }

    // epilogue: exp(acc - m) -> P fp16; deterministic Z partials
    __half* Pb = g_P + (size_t)b * NN * NN;
#pragma unroll
    for (int mi = 0; mi < 4; ++mi) {
        int j = j0 + wm + mi * 16 + g;
        float m0 = dec_f(g_rowmax[b * NN + j]);
        float m1 = dec_f(g_rowmax[b * NN + j + 8]);
        float s0 = 0.f, s1 = 0.f;
#pragma unroll
        for (int ni = 0; ni < 4; ++ni) {
            int i = i0 + wn + ni * 8 + t * 2;
            float e0 = fast_exp(acc[mi][ni][0] - m0);
            float e1 = fast_exp(acc[mi][ni][1] - m0);
            float e2 = fast_exp(acc[mi][ni][2] - m1);
            float e3 = fast_exp(acc[mi][ni][3] - m1);
            s0 += e0 + e1;
            s1 += e2 + e3;
            __half2 h0 = __floats2half2_rn(e0, e1);
            __half2 h1 = __floats2half2_rn(e2, e3);
            *(unsigned*)&Pb[(size_t)j * NN + i]       = *(unsigned*)&h0;
            *(unsigned*)&Pb[(size_t)(j + 8) * NN + i] = *(unsigned*)&h1;
        }
        s0 += __shfl_xor_sync(0xffffffffu, s0, 1);
        s0 += __shfl_xor_sync(0xffffffffu, s0, 2);
        s1 += __shfl_xor_sync(0xffffffffu, s1, 1);
        s1 += __shfl_xor_sync(0xffffffffu, s1, 2);
        if (t == 0) {
            spart[wm + mi * 16 + g][warp & 3]     = s0;
            spart[wm + mi * 16 + g + 8][warp & 3] = s1;
        }
    }
    __syncthreads();
    if (tid < 128) {
        float z = ((spart[tid][0] + spart[tid][1]) + (spart[tid][2] + spart[tid][3]));
        g_Zpart[((size_t)b * NN + j0 + tid) * 32 + blockIdx.x] = z;
    }
}

// ================= K3z: reduce Z partials (fixed order), fold 1/Z into g fp16 =====
__global__ __launch_bounds__(256) void k3z_scale()
{
    const int warp = threadIdx.x >> 5, lane = threadIdx.x & 31;
    const size_t row = (size_t)blockIdx.x * 8 + warp;
    float v = g_Zpart[row * 32 + lane];
#pragma unroll
    for (int o = 16; o; o >>= 1) v += __shfl_xor_sync(0xffffffffu, v, o);
    const float z = 1.0f / v;

    const float4* gv4 = (const float4*)(g_gv + row * CHH);
    uint2* gh2 = (uint2*)(g_gvh + row * CHH);
    float4 w = gv4[lane];
    __half2 h0 = __floats2half2_rn(w.x * z, w.y * z);
    __half2 h1 = __floats2half2_rn(w.z * z, w.w * z);
    gh2[lane] = make_uint2(*(unsigned*)&h0, *(unsigned*)&h1);
}

// ================= K4: O[i][c] = sum_j P[j][i]*g'[j][c]  (fp16 mma, ldmatrix) =====
#define K4BK  32
#define K4_PA 72
#define K4_PB 136
__global__ __launch_bounds__(256) void k4_av_fp16()
{
    __shared__ __align__(16) __half As[3][K4BK * K4_PA];
    __shared__ __align__(16) __half Bs[3][K4BK * K4_PB];
    const int b  = blockIdx.y;
    const int i0 = blockIdx.x * 64;
    const int tid = threadIdx.x;
    const int warp = tid >> 5, lane = tid & 31;
    const int g = lane >> 2, t = lane & 3;
    const int wm = (warp >> 2) * 32;
    const int wn = (warp & 3) * 32;
    const __half* Pb = g_P   + (size_t)b * NN * NN;
    const __half* gh = g_gvh + (size_t)b * NN * CHH;

    const int krA = (lane & 7) + ((lane & 16) ? 8 : 0);
    const int mcA = (lane & 8) ? 8 : 0;
    const int krB = (lane & 7) + ((lane & 8) ? 8 : 0);
    const int ncB = (lane & 16) ? 8 : 0;

    const int arow = tid >> 3, acol = (tid & 7) * 8;
    const int brow0 = tid >> 4, bcol = (tid & 15) * 8;
    const int brow1 = brow0 + 16;

    float acc[2][4][4] = {};

#define K4_LOAD(st, j0)                                                          \
    {                                                                            \
        cp16(&As[st][arow * K4_PA + acol],  Pb + (size_t)((j0) + arow) * NN + i0 + acol); \
        cp16(&Bs[st][brow0 * K4_PB + bcol], gh + (size_t)((j0) + brow0) * CHH + bcol);    \
        cp16(&Bs[st][brow1 * K4_PB + bcol], gh + (size_t)((j0) + brow1) * CHH + bcol);    \
    }

    K4_LOAD(0, 0);
    asm volatile("cp.async.commit_group;");
    K4_LOAD(1, K4BK);
    asm volatile("cp.async.commit_group;");

    int s = 0;
#pragma unroll 1
    for (int it = 0; it < NN / K4BK; ++it) {
        asm volatile("cp.async.wait_group 1;");
        __syncthreads();

        if (it + 2 < NN / K4BK) {
            int st = s + 2; if (st >= 3) st -= 3;
            K4_LOAD(st, (it + 2) * K4BK);
        }
        asm volatile("cp.async.commit_group;");

#pragma unroll
        for (int ks = 0; ks < K4BK; ks += 16) {
            unsigned a[2][4], bq[2][4];
#pragma unroll
            for (int mi = 0; mi < 2; ++mi)
                ldsm4t(a[mi], &As[s][(ks + krA) * K4_PA + wm + mi * 16 + mcA]);
#pragma unroll
            for (int nb = 0; nb < 2; ++nb)
                ldsm4t(bq[nb], &Bs[s][(ks + krB) * K4_PB + wn + nb * 16 + ncB]);
#pragma unroll
            for (int mi = 0; mi < 2; ++mi)
#pragma unroll
                for (int ni = 0; ni < 4; ++ni)
                    mma_fp16(acc[mi][ni], a[mi], &bq[ni >> 1][(ni & 1) * 2]);
        }
        __syncthreads();
        if (++s == 3) s = 0;
    }

    float* Ob = g_O + (size_t)b * NN * CHH;
#pragma unroll
    for (int mi = 0; mi < 2; ++mi)
#pragma unroll
        for (int ni = 0; ni < 4; ++ni) {
            int i = i0 + wm + mi * 16 + g;
            int c = wn + ni * 8 + t * 2;
            *(float2*)&Ob[(size_t)i * CHH + c] =
                make_float2(acc[mi][ni][0], acc[mi][ni][1]);
            *(float2*)&Ob[(size_t)(i + 8) * CHH + c] =
                make_float2(acc[mi][ni][2], acc[mi][ni][3]);
        }
}

// ================= K5: final projection + bias + residual (SIMT) =================
__device__ __forceinline__ void gemm_step(const float* __restrict__ As,
                                          const float* __restrict__ Bs,
                                          float (&acc)[8][8], int ty, int tx) {
#pragma unroll
    for (int k = 0; k < BK; ++k) {
        float a[8], b[8];
        *(float4*)&a[0] = *(const float4*)&As[k * SPITCH + ty * 8];
        *(float4*)&a[4] = *(const float4*)&As[k * SPITCH + ty * 8 + 4];
        *(float4*)&b[0] = *(const float4*)&Bs[k * SPITCH + tx * 8];
        *(float4*)&b[4] = *(const float4*)&Bs[k * SPITCH + tx * 8 + 4];
#pragma unroll
        for (int r = 0; r < 8; ++r)
#pragma unroll
            for (int c = 0; c < 8; ++c)
                acc[r][c] = fmaf(a[r], b[c], acc[r][c]);
    }
}

__global__ __launch_bounds__(256) void k5_out(
    const float* __restrict__ x,
    const float* __restrict__ Ww, const float* __restrict__ Wb,
    float* __restrict__ out)
{
    __shared__ float As[BK * SPITCH];
    __shared__ float Bs[BK * SPITCH];
    const int b  = blockIdx.z;
    const int o0 = blockIdx.y * TILE;
    const int n0 = blockIdx.x * TILE;
    const int tid = threadIdx.x, ty = tid >> 4, tx = tid & 15;
    const float* Ob = g_O + (size_t)b * NN * CHH;

    float acc[8][8] = {};
    for (int k0 = 0; k0 < CHH; k0 += BK) {
#pragma unroll
        for (int it = 0; it < 2; ++it) {
            int idx = tid + it * 256;
            int kk4 = idx & 3, oo = idx >> 2;
            float4 v = *(const float4*)(Ww + (size_t)(o0 + oo) * CHH + k0 + kk4 * 4);
            As[(kk4 * 4 + 0) * SPITCH + oo] = v.x;
            As[(kk4 * 4 + 1) * SPITCH + oo] = v.y;
            As[(kk4 * 4 + 2) * SPITCH + oo] = v.z;
            As[(kk4 * 4 + 3) * SPITCH + oo] = v.w;
        }
#pragma unroll
        for (int it = 0; it < 2; ++it) {
            int idx = tid + it * 256;
            int kk4 = idx & 3, nn = idx >> 2;
            float4 v = *(const float4*)(Ob + (size_t)(n0 + nn) * CHH + k0 + kk4 * 4);
            Bs[(kk4 * 4 + 0) * SPITCH + nn] = v.x;
            Bs[(kk4 * 4 + 1) * SPITCH + nn] = v.y;
            Bs[(kk4 * 4 + 2) * SPITCH + nn] = v.z;
            Bs[(kk4 * 4 + 3) * SPITCH + nn] = v.w;
        }
        __syncthreads();
        gemm_step(As, Bs, acc, ty, tx);
        __syncthreads();
    }

#pragma unroll
    for (int r = 0; r < 8; ++r) {
        int o = o0 + ty * 8 + r;
        float bb = Wb[o];
        const float* xr = x   + (size_t)b * CC * NN + (size_t)o * NN + n0 + tx * 8;
        float*       yr = out + (size_t)b * CC * NN + (size_t)o * NN + n0 + tx * 8;
        float4 x0 = *(const float4*)xr;
        float4 x1 = *(const float4*)(xr + 4);
        *(float4*)yr = make_float4(acc[r][0] + bb + x0.x, acc[r][1] + bb + x0.y,
                                   acc[r][2] + bb + x0.z, acc[r][3] + bb + x0.w);
        *(float4*)(yr + 4) = make_float4(acc[r][4] + bb + x1.x, acc[r][5] + bb + x1.y,
                                         acc[r][6] + bb + x1.z, acc[r][7] + bb + x1.w);
    }
}

// ================= launch =================
extern "C" void kernel_launch(void* const* d_in, const int* in_sizes, int n_in,
                              void* d_out, int out_size) {
    const float* x  = (const float*)d_in[0];
    const float* tw = (const float*)d_in[1];
    const float* tb = (const float*)d_in[2];
    const float* pw = (const float*)d_in[3];
    const float* pb = (const float*)d_in[4];
    const float* gw = (const float*)d_in[5];
    const float* gb = (const float*)d_in[6];
    const float* Ww = (const float*)d_in[7];
    const float* Wb = (const float*)d_in[8];
    float* out = (float*)d_out;

    k0_init       <<<dim3(BB * NN / 256),              256>>>();
    k0x_split     <<<dim3(BB * CC * NN / 4 / 256),     256>>>(x);
    k0w_split     <<<dim3(3 * CC * CHH / 256),         256>>>(tw, pw, gw);
    k1_mma        <<<dim3(NN / 64, 3, BB),             256>>>(tb, pb, gb);
    k2a_rowmax    <<<dim3(NN / 128, NN / 128, BB),     256>>>();
    k2b_scores_exp<<<dim3(NN / 128, NN / 128, BB),     256>>>();
    k3z_scale     <<<dim3(BB * NN / 8),                256>>>();
    k4_av_fp16    <<<dim3(NN / 64, BB),                256>>>();
    k5_out        <<<dim3(NN / TILE, CC / TILE, BB),   256>>>(x, Ww, Wb, out);
}

// round 9
// speedup vs baseline: 1.0972x; 1.0972x over previous
#include <cuda_runtime.h>
#include <cuda_bf16.h>
#include <cuda_fp16.h>

#define BB   4
#define CC   256
#define CHH  128
#define NN   4096

#define BK     16

// ---------------- scratch ----------------
__device__ float    g_gv   [(size_t)BB * NN * CHH];   // g fp32 (k1 out, k3 in)
__device__ __half   g_gvh  [(size_t)BB * NN * CHH];   // g/Z fp16 (k3 out, k4 in)
__device__ float    g_S    [(size_t)BB * NN * NN];    // scores fp32 [b][j][i]
__device__ __half   g_P    [(size_t)BB * NN * NN];    // probs fp16 [b][j][i]
__device__ unsigned g_rowmax[BB * NN];
// attention output as split bf16 (k4 out, k5 in)
__device__ __nv_bfloat16 g_OB [(size_t)BB * NN * CHH];
__device__ __nv_bfloat16 g_OS [(size_t)BB * NN * CHH];
// split-bf16 theta/phi (big + residual)
__device__ __nv_bfloat16 g_thB[(size_t)BB * NN * CHH];
__device__ __nv_bfloat16 g_thS[(size_t)BB * NN * CHH];
__device__ __nv_bfloat16 g_phB[(size_t)BB * NN * CHH];
__device__ __nv_bfloat16 g_phS[(size_t)BB * NN * CHH];
// split-bf16 x, transposed proj weights, and Ww
__device__ __nv_bfloat16 g_xB [(size_t)BB * CC * NN];
__device__ __nv_bfloat16 g_xS [(size_t)BB * CC * NN];
__device__ __nv_bfloat16 g_wTB[3 * CC * CHH];          // [proj][c][o]
__device__ __nv_bfloat16 g_wTS[3 * CC * CHH];
__device__ __nv_bfloat16 g_WoB[CC * CHH];              // Ww [o][c]
__device__ __nv_bfloat16 g_WoS[CC * CHH];

// ---------------- fast exp (FFMA-only, x <= ~0) ----------------
__device__ __forceinline__ float fast_exp(float x) {
    float t = fmaxf(x * 1.4426950408889634f, -120.0f);
    float z = t + 12582912.0f;
    int   e = __float_as_int(z);
    float f = t - (z - 12582912.0f);
    float p = 1.3333558e-3f;
    p = fmaf(p, f, 9.6181291e-3f);
    p = fmaf(p, f, 5.5504109e-2f);
    p = fmaf(p, f, 2.4022651e-1f);
    p = fmaf(p, f, 6.9314718e-1f);
    p = fmaf(p, f, 1.0f);
    return __int_as_float((e << 23) + __float_as_int(p));
}

// ---------------- monotonic float<->uint for atomicMax ----------------
__device__ __forceinline__ unsigned enc_f(float v) {
    unsigned b = __float_as_uint(v);
    return (b & 0x80000000u) ? ~b : (b | 0x80000000u);
}
__device__ __forceinline__ float dec_f(unsigned u) {
    return (u & 0x80000000u) ? __uint_as_float(u & 0x7fffffffu)
                             : __uint_as_float(~u);
}

// ---------------- tensor-core helpers ----------------
__device__ __forceinline__ void mma_bf16(float* d, const unsigned* a, const unsigned* b) {
    asm volatile("mma.sync.aligned.m16n8k16.row.col.f32.bf16.bf16.f32 "
                 "{%0,%1,%2,%3}, {%4,%5,%6,%7}, {%8,%9}, {%0,%1,%2,%3};"
                 : "+f"(d[0]), "+f"(d[1]), "+f"(d[2]), "+f"(d[3])
                 : "r"(a[0]), "r"(a[1]), "r"(a[2]), "r"(a[3]),
                   "r"(b[0]), "r"(b[1]));
}
__device__ __forceinline__ void mma_fp16(float* d, const unsigned* a, const unsigned* b) {
    asm volatile("mma.sync.aligned.m16n8k16.row.col.f32.f16.f16.f32 "
                 "{%0,%1,%2,%3}, {%4,%5,%6,%7}, {%8,%9}, {%0,%1,%2,%3};"
                 : "+f"(d[0]), "+f"(d[1]), "+f"(d[2]), "+f"(d[3])
                 : "r"(a[0]), "r"(a[1]), "r"(a[2]), "r"(a[3]),
                   "r"(b[0]), "r"(b[1]));
}
__device__ __forceinline__ void ldsm4t(unsigned* r, const void* smem) {
    unsigned a = (unsigned)__cvta_generic_to_shared(smem);
    asm volatile("ldmatrix.sync.aligned.m8n8.x4.trans.shared.b16 {%0,%1,%2,%3}, [%4];"
                 : "=r"(r[0]), "=r"(r[1]), "=r"(r[2]), "=r"(r[3]) : "r"(a));
}
__device__ __forceinline__ void ldsm4(unsigned* r, const void* smem) {
    unsigned a = (unsigned)__cvta_generic_to_shared(smem);
    asm volatile("ldmatrix.sync.aligned.m8n8.x4.shared.b16 {%0,%1,%2,%3}, [%4];"
                 : "=r"(r[0]), "=r"(r[1]), "=r"(r[2]), "=r"(r[3]) : "r"(a));
}
__device__ __forceinline__ void cp16(void* smem, const void* g) {
    unsigned a = (unsigned)__cvta_generic_to_shared(smem);
    asm volatile("cp.async.cg.shared.global [%0], [%1], 16;" :: "r"(a), "l"(g));
}
// split a float2 into packed bf16x2 (big) + packed bf16x2 (residual)
__device__ __forceinline__ void split2(float v0, float v1, unsigned& big, unsigned& sml) {
    asm("cvt.rn.bf16x2.f32 %0, %1, %2;" : "=r"(big) : "f"(v1), "f"(v0));
    float b0 = __uint_as_float(big << 16);
    float b1 = __uint_as_float(big & 0xffff0000u);
    float r0 = v0 - b0, r1 = v1 - b1;
    asm("cvt.rn.bf16x2.f32 %0, %1, %2;" : "=r"(sml) : "f"(r1), "f"(r0));
}

// ================= K0: init rowmax =================
__global__ __launch_bounds__(256) void k0_init() {
    g_rowmax[blockIdx.x * 256 + threadIdx.x] = 0u;
}

// ================= K0x: split x -> bf16 big/small planes =================
__global__ __launch_bounds__(256) void k0x_split(const float* __restrict__ x) {
    size_t i4 = (size_t)blockIdx.x * 256 + threadIdx.x;
    float4 v = ((const float4*)x)[i4];
    unsigned b0, s0, b1, s1;
    split2(v.x, v.y, b0, s0);
    split2(v.z, v.w, b1, s1);
    ((uint2*)g_xB)[i4] = make_uint2(b0, b1);
    ((uint2*)g_xS)[i4] = make_uint2(s0, s1);
}

// ================= K0w: split weights (proj transposed; Ww direct) =================
__global__ __launch_bounds__(256) void k0w_split(
    const float* __restrict__ tw, const float* __restrict__ pw,
    const float* __restrict__ gw, const float* __restrict__ Ww) {
    int idx = blockIdx.x * 256 + threadIdx.x;   // 4*256*128
    if (idx < 3 * CC * CHH) {
        int o = idx & 127;
        int c = (idx >> 7) & 255;
        int p = idx >> 15;
        const float* w = p == 0 ? tw : (p == 1 ? pw : gw);
        float v = w[o * CC + c];
        __nv_bfloat16 big = __float2bfloat16(v);
        g_wTB[idx] = big;
        g_wTS[idx] = __float2bfloat16(v - __bfloat162float(big));
    } else {
        int j = idx - 3 * CC * CHH;             // Ww[o][c] flat, no transpose
        float v = Ww[j];
        __nv_bfloat16 big = __float2bfloat16(v);
        g_WoB[j] = big;
        g_WoS[j] = __float2bfloat16(v - __bfloat162float(big));
    }
}

// ================= K1: projections via split-bf16 x3 mma =================
#define K1_PA 72
#define K1_PB 136
__global__ __launch_bounds__(256) void k1_mma(
    const float* __restrict__ tb, const float* __restrict__ pb,
    const float* __restrict__ gb)
{
    __shared__ __align__(16) __nv_bfloat16 As[3][2][BK * K1_PA];
    __shared__ __align__(16) __nv_bfloat16 Bs[3][2][BK * K1_PB];
    const int b    = blockIdx.z;
    const int proj = blockIdx.y;
    const int i0   = blockIdx.x * 64;
    const int tid  = threadIdx.x;
    const int warp = tid >> 5, lane = tid & 31;
    const int g = lane >> 2, t = lane & 3;
    const int wm = (warp >> 2) * 32;
    const int wn = (warp & 3) * 32;

    const __nv_bfloat16* xB = g_xB + (size_t)b * CC * NN;
    const __nv_bfloat16* xS = g_xS + (size_t)b * CC * NN;
    const __nv_bfloat16* wB = g_wTB + (size_t)proj * CC * CHH;
    const __nv_bfloat16* wS = g_wTS + (size_t)proj * CC * CHH;
    const float* bias = proj == 0 ? tb : (proj == 1 ? pb : gb);

    const int krA = (lane & 7) + ((lane & 16) ? 8 : 0);
    const int mcA = (lane & 8) ? 8 : 0;
    const int krB = (lane & 7) + ((lane & 8) ? 8 : 0);
    const int ncB = (lane & 16) ? 8 : 0;

    const int av  = tid >> 7, ac = tid & 127;
    const int ar  = ac >> 3, acol = (ac & 7) * 8;
    float acc[2][4][4] = {};

#define K1_LOAD(st, k0)                                                              \
    {                                                                                \
        const __nv_bfloat16* xa = av ? xS : xB;                                      \
        cp16(&As[st][av][ar * K1_PA + acol],                                         \
             xa + (size_t)((k0) + ar) * NN + i0 + acol);                             \
        _Pragma("unroll")                                                            \
        for (int q = 0; q < 2; ++q) {                                                \
            int idx = tid + q * 256;                                                 \
            int bv = idx >> 8, cc = idx & 255;                                       \
            int br = cc >> 4, bcol = (cc & 15) * 8;                                  \
            const __nv_bfloat16* wa = bv ? wS : wB;                                  \
            cp16(&Bs[st][bv][br * K1_PB + bcol],                                     \
                 wa + (size_t)((k0) + br) * CHH + bcol);                             \
        }                                                                            \
    }

    K1_LOAD(0, 0);
    asm volatile("cp.async.commit_group;");
    K1_LOAD(1, BK);
    asm volatile("cp.async.commit_group;");

    int s = 0;
#pragma unroll 1
    for (int it = 0; it < CC / BK; ++it) {
        asm volatile("cp.async.wait_group 1;");
        __syncthreads();

        if (it + 2 < CC / BK) {
            int st = s + 2; if (st >= 3) st -= 3;
            K1_LOAD(st, (it + 2) * BK);
        }
        asm volatile("cp.async.commit_group;");

        unsigned aB[2][4], aS[2][4], bB[2][4], bS[2][4];
#pragma unroll
        for (int mi = 0; mi < 2; ++mi) {
            ldsm4t(aB[mi], &As[s][0][krA * K1_PA + wm + mi * 16 + mcA]);
            ldsm4t(aS[mi], &As[s][1][krA * K1_PA + wm + mi * 16 + mcA]);
        }
#pragma unroll
        for (int nb = 0; nb < 2; ++nb) {
            ldsm4t(bB[nb], &Bs[s][0][krB * K1_PB + wn + nb * 16 + ncB]);
            ldsm4t(bS[nb], &Bs[s][1][krB * K1_PB + wn + nb * 16 + ncB]);
        }
#pragma unroll
        for (int mi = 0; mi < 2; ++mi)
#pragma unroll
            for (int ni = 0; ni < 4; ++ni) {
                mma_bf16(acc[mi][ni], aB[mi], &bS[ni >> 1][(ni & 1) * 2]);
                mma_bf16(acc[mi][ni], aS[mi], &bB[ni >> 1][(ni & 1) * 2]);
                mma_bf16(acc[mi][ni], aB[mi], &bB[ni >> 1][(ni & 1) * 2]);
            }
        __syncthreads();
        if (++s == 3) s = 0;
    }

    if (proj < 2) {
        __nv_bfloat16* outB = proj == 0 ? g_thB : g_phB;
        __nv_bfloat16* outS = proj == 0 ? g_thS : g_phS;
        size_t base = (size_t)b * NN * CHH;
#pragma unroll
        for (int mi = 0; mi < 2; ++mi) {
            int i = i0 + wm + mi * 16 + g;
#pragma unroll
            for (int ni = 0; ni < 4; ++ni) {
                int o = wn + ni * 8 + t * 2;
                float b0 = bias[o], b1 = bias[o + 1];
                unsigned pbv, psv;
                split2(acc[mi][ni][0] + b0, acc[mi][ni][1] + b1, pbv, psv);
                *(unsigned*)&outB[base + (size_t)i * CHH + o] = pbv;
                *(unsigned*)&outS[base + (size_t)i * CHH + o] = psv;
                split2(acc[mi][ni][2] + b0, acc[mi][ni][3] + b1, pbv, psv);
                *(unsigned*)&outB[base + (size_t)(i + 8) * CHH + o] = pbv;
                *(unsigned*)&outS[base + (size_t)(i + 8) * CHH + o] = psv;
            }
        }
    } else {
        float* ob = g_gv + (size_t)b * NN * CHH;
#pragma unroll
        for (int mi = 0; mi < 2; ++mi) {
            int i = i0 + wm + mi * 16 + g;
#pragma unroll
            for (int ni = 0; ni < 4; ++ni) {
                int o = wn + ni * 8 + t * 2;
                float b0 = bias[o], b1 = bias[o + 1];
                *(float2*)&ob[(size_t)i * CHH + o] =
                    make_float2(acc[mi][ni][0] + b0, acc[mi][ni][1] + b1);
                *(float2*)&ob[(size_t)(i + 8) * CHH + o] =
                    make_float2(acc[mi][ni][2] + b0, acc[mi][ni][3] + b1);
            }
        }
    }
}

// ================= K2: S = theta . phi^T (split-bf16 x3, ldmatrix, fused rowmax) ===
#define K2P 24
__global__ __launch_bounds__(256) void k2_scores_mma()
{
    __shared__ __align__(16) __nv_bfloat16 sm[2][4][128 * K2P];
    const int b  = blockIdx.z;
    const int j0 = blockIdx.y * 128;
    const int i0 = blockIdx.x * 128;
    const int tid = threadIdx.x;
    const int warp = tid >> 5, lane = tid & 31;
    const int g = lane >> 2, t = lane & 3;
    const int wm = (warp >> 2) * 64;
    const int wn = (warp & 3) * 32;
    const size_t baseJ = (size_t)b * NN * CHH + (size_t)j0 * CHH;
    const size_t baseI = (size_t)b * NN * CHH + (size_t)i0 * CHH;
    const __nv_bfloat16* thB = g_thB + baseJ;
    const __nv_bfloat16* thS = g_thS + baseJ;
    const __nv_bfloat16* phB = g_phB + baseI;
    const __nv_bfloat16* phS = g_phS + baseI;

    const int arow = (lane & 7) + ((lane & 8) ? 8 : 0);
    const int akof = (lane & 16) ? 8 : 0;
    const int brow = (lane & 7) + ((lane & 16) ? 8 : 0);
    const int bkof = (lane & 8) ? 8 : 0;

    float acc[4][4][4] = {};

    const int lrow = tid >> 1, lkc = (tid & 1) * 8;
#define K2_LOAD(st, k0)                                                        \
    {                                                                          \
        cp16(&sm[st][0][lrow * K2P + lkc], thB + (size_t)lrow * CHH + (k0) + lkc); \
        cp16(&sm[st][1][lrow * K2P + lkc], thS + (size_t)lrow * CHH + (k0) + lkc); \
        cp16(&sm[st][2][lrow * K2P + lkc], phB + (size_t)lrow * CHH + (k0) + lkc); \
        cp16(&sm[st][3][lrow * K2P + lkc], phS + (size_t)lrow * CHH + (k0) + lkc); \
    }

    K2_LOAD(0, 0);
    asm volatile("cp.async.commit_group;");

#pragma unroll 1
    for (int it = 0; it < CHH / BK; ++it) {
        const int s = it & 1;
        if (it + 1 < CHH / BK) K2_LOAD(s ^ 1, (it + 1) * BK);
        asm volatile("cp.async.commit_group;");
        asm volatile("cp.async.wait_group 1;");
        __syncthreads();

        const __nv_bfloat16* AB = sm[s][0];
        const __nv_bfloat16* AS = sm[s][1];
        const __nv_bfloat16* PB = sm[s][2];
        const __nv_bfloat16* PS = sm[s][3];

        unsigned aB[4][4], aS[4][4], bB[2][4], bS[2][4];
#pragma unroll
        for (int mi = 0; mi < 4; ++mi) {
            ldsm4(aB[mi], &AB[(wm + mi * 16 + arow) * K2P + akof]);
            ldsm4(aS[mi], &AS[(wm + mi * 16 + arow) * K2P + akof]);
        }
#pragma unroll
        for (int nb = 0; nb < 2; ++nb) {
            ldsm4(bB[nb], &PB[(wn + nb * 16 + brow) * K2P + bkof]);
            ldsm4(bS[nb], &PS[(wn + nb * 16 + brow) * K2P + bkof]);
        }
#pragma unroll
        for (int mi = 0; mi < 4; ++mi)
#pragma unroll
            for (int ni = 0; ni < 4; ++ni) {
                mma_bf16(acc[mi][ni], aB[mi], &bS[ni >> 1][(ni & 1) * 2]);
                mma_bf16(acc[mi][ni], aS[mi], &bB[ni >> 1][(ni & 1) * 2]);
                mma_bf16(acc[mi][ni], aB[mi], &bB[ni >> 1][(ni & 1) * 2]);
            }
        __syncthreads();
    }

    float* Sb = g_S + (size_t)b * NN * NN;
#pragma unroll
    for (int mi = 0; mi < 4; ++mi) {
        int j = j0 + wm + mi * 16 + g;
        float r0 = -3.0e38f, r1 = -3.0e38f;
#pragma unroll
        for (int ni = 0; ni < 4; ++ni) {
            int i = i0 + wn + ni * 8 + t * 2;
            *(float2*)&Sb[(size_t)j * NN + i] =
                make_float2(acc[mi][ni][0], acc[mi][ni][1]);
            *(float2*)&Sb[(size_t)(j + 8) * NN + i] =
                make_float2(acc[mi][ni][2], acc[mi][ni][3]);
            r0 = fmaxf(r0, fmaxf(acc[mi][ni][0], acc[mi][ni][1]));
            r1 = fmaxf(r1, fmaxf(acc[mi][ni][2], acc[mi][ni][3]));
        }
        r0 = fmaxf(r0, __shfl_xor_sync(0xffffffffu, r0, 1));
        r0 = fmaxf(r0, __shfl_xor_sync(0xffffffffu, r0, 2));
        r1 = fmaxf(r1, __shfl_xor_sync(0xffffffffu, r1, 1));
        r1 = fmaxf(r1, __shfl_xor_sync(0xffffffffu, r1, 2));
        if (t == 0) {
            atomicMax(&g_rowmax[b * NN + j],     enc_f(r0));
            atomicMax(&g_rowmax[b * NN + j + 8], enc_f(r1));
        }
    }
}

// ================= K3: read S fp32, write P fp16; fold 1/Z into g (fp16) =========
__global__ __launch_bounds__(256) void k3_softmax()
{
    const int warp = threadIdx.x >> 5, lane = threadIdx.x & 31;
    const size_t row = (size_t)blockIdx.x * 8 + warp;
    const float mx = dec_f(g_rowmax[row]);
    const float4* S4 = (const float4*)(g_S + row * NN);
    uint2* P2 = (uint2*)(g_P + row * NN);

    float s = 0.f;
#pragma unroll 4
    for (int it = lane; it < NN / 4; it += 32) {
        float4 v = S4[it];
        v.x = fast_exp(v.x - mx);
        v.y = fast_exp(v.y - mx);
        v.z = fast_exp(v.z - mx);
        v.w = fast_exp(v.w - mx);
        s += (v.x + v.y) + (v.z + v.w);
        __half2 h0 = __floats2half2_rn(v.x, v.y);
        __half2 h1 = __floats2half2_rn(v.z, v.w);
        P2[it] = make_uint2(*(unsigned*)&h0, *(unsigned*)&h1);
    }
#pragma unroll
    for (int o = 16; o; o >>= 1) s += __shfl_xor_sync(0xffffffffu, s, o);
    const float z = 1.0f / s;

    const float4* gv4 = (const float4*)(g_gv + row * CHH);
    uint2* gh2 = (uint2*)(g_gvh + row * CHH);
    float4 v = gv4[lane];
    __half2 h0 = __floats2half2_rn(v.x * z, v.y * z);
    __half2 h1 = __floats2half2_rn(v.z * z, v.w * z);
    gh2[lane] = make_uint2(*(unsigned*)&h0, *(unsigned*)&h1);
}

// ================= K4: O[i][c] = sum_j P[j][i]*g'[j][c]  (fp16 mma, ldmatrix) =====
// epilogue writes O as split-bf16 for the tensorized K5
#define K4BK  32
#define K4_PA 72
#define K4_PB 136
__global__ __launch_bounds__(256) void k4_av_fp16()
{
    __shared__ __align__(16) __half As[3][K4BK * K4_PA];
    __shared__ __align__(16) __half Bs[3][K4BK * K4_PB];
    const int b  = blockIdx.y;
    const int i0 = blockIdx.x * 64;
    const int tid = threadIdx.x;
    const int warp = tid >> 5, lane = tid & 31;
    const int g = lane >> 2, t = lane & 3;
    const int wm = (warp >> 2) * 32;
    const int wn = (warp & 3) * 32;
    const __half* Pb = g_P   + (size_t)b * NN * NN;
    const __half* gh = g_gvh + (size_t)b * NN * CHH;

    const int krA = (lane & 7) + ((lane & 16) ? 8 : 0);
    const int mcA = (lane & 8) ? 8 : 0;
    const int krB = (lane & 7) + ((lane & 8) ? 8 : 0);
    const int ncB = (lane & 16) ? 8 : 0;

    const int arow = tid >> 3, acol = (tid & 7) * 8;
    const int brow0 = tid >> 4, bcol = (tid & 15) * 8;
    const int brow1 = brow0 + 16;

    float acc[2][4][4] = {};

#define K4_LOAD(st, j0)                                                          \
    {                                                                            \
        cp16(&As[st][arow * K4_PA + acol],  Pb + (size_t)((j0) + arow) * NN + i0 + acol); \
        cp16(&Bs[st][brow0 * K4_PB + bcol], gh + (size_t)((j0) + brow0) * CHH + bcol);    \
        cp16(&Bs[st][brow1 * K4_PB + bcol], gh + (size_t)((j0) + brow1) * CHH + bcol);    \
    }

    K4_LOAD(0, 0);
    asm volatile("cp.async.commit_group;");
    K4_LOAD(1, K4BK);
    asm volatile("cp.async.commit_group;");

    int s = 0;
#pragma unroll 1
    for (int it = 0; it < NN / K4BK; ++it) {
        asm volatile("cp.async.wait_group 1;");
        __syncthreads();

        if (it + 2 < NN / K4BK) {
            int st = s + 2; if (st >= 3) st -= 3;
            K4_LOAD(st, (it + 2) * K4BK);
        }
        asm volatile("cp.async.commit_group;");

#pragma unroll
        for (int ks = 0; ks < K4BK; ks += 16) {
            unsigned a[2][4], bq[2][4];
#pragma unroll
            for (int mi = 0; mi < 2; ++mi)
                ldsm4t(a[mi], &As[s][(ks + krA) * K4_PA + wm + mi * 16 + mcA]);
#pragma unroll
            for (int nb = 0; nb < 2; ++nb)
                ldsm4t(bq[nb], &Bs[s][(ks + krB) * K4_PB + wn + nb * 16 + ncB]);
#pragma unroll
            for (int mi = 0; mi < 2; ++mi)
#pragma unroll
                for (int ni = 0; ni < 4; ++ni)
                    mma_fp16(acc[mi][ni], a[mi], &bq[ni >> 1][(ni & 1) * 2]);
        }
        __syncthreads();
        if (++s == 3) s = 0;
    }

    __nv_bfloat16* OB = g_OB + (size_t)b * NN * CHH;
    __nv_bfloat16* OS = g_OS + (size_t)b * NN * CHH;
#pragma unroll
    for (int mi = 0; mi < 2; ++mi)
#pragma unroll
        for (int ni = 0; ni < 4; ++ni) {
            int i = i0 + wm + mi * 16 + g;
            int c = wn + ni * 8 + t * 2;
            unsigned pb, ps;
            split2(acc[mi][ni][0], acc[mi][ni][1], pb, ps);
            *(unsigned*)&OB[(size_t)i * CHH + c] = pb;
            *(unsigned*)&OS[(size_t)i * CHH + c] = ps;
            split2(acc[mi][ni][2], acc[mi][ni][3], pb, ps);
            *(unsigned*)&OB[(size_t)(i + 8) * CHH + c] = pb;
            *(unsigned*)&OS[(size_t)(i + 8) * CHH + c] = ps;
        }
}

// ================= K5: out = Ww.O + Wb + x  (split-bf16 x3 mma) ==================
// tile 128(o) x 128(n), k=ch 128; 8 warps = 2(m:64) x 4(n:32); same shape as K2
__global__ __launch_bounds__(256) void k5_mma(
    const float* __restrict__ x, const float* __restrict__ Wb,
    float* __restrict__ out)
{
    __shared__ __align__(16) __nv_bfloat16 sm[2][4][128 * K2P];  // WoB, WoS, OB, OS
    const int b  = blockIdx.z;
    const int o0 = blockIdx.y * 128;
    const int n0 = blockIdx.x * 128;
    const int tid = threadIdx.x;
    const int warp = tid >> 5, lane = tid & 31;
    const int g = lane >> 2, t = lane & 3;
    const int wm = (warp >> 2) * 64;
    const int wn = (warp & 3) * 32;
    const __nv_bfloat16* WoB = g_WoB + (size_t)o0 * CHH;
    const __nv_bfloat16* WoS = g_WoS + (size_t)o0 * CHH;
    const __nv_bfloat16* OB  = g_OB + (size_t)b * NN * CHH + (size_t)n0 * CHH;
    const __nv_bfloat16* OS  = g_OS + (size_t)b * NN * CHH + (size_t)n0 * CHH;

    const int arow = (lane & 7) + ((lane & 8) ? 8 : 0);
    const int akof = (lane & 16) ? 8 : 0;
    const int brow = (lane & 7) + ((lane & 16) ? 8 : 0);
    const int bkof = (lane & 8) ? 8 : 0;

    float acc[4][4][4] = {};

    const int lrow = tid >> 1, lkc = (tid & 1) * 8;
#define K5_LOAD(st, k0)                                                        \
    {                                                                          \
        cp16(&sm[st][0][lrow * K2P + lkc], WoB + (size_t)lrow * CHH + (k0) + lkc); \
        cp16(&sm[st][1][lrow * K2P + lkc], WoS + (size_t)lrow * CHH + (k0) + lkc); \
        cp16(&sm[st][2][lrow * K2P + lkc], OB  + (size_t)lrow * CHH + (k0) + lkc); \
        cp16(&sm[st][3][lrow * K2P + lkc], OS  + (size_t)lrow * CHH + (k0) + lkc); \
    }

    K5_LOAD(0, 0);
    asm volatile("cp.async.commit_group;");

#pragma unroll 1
    for (int it = 0; it < CHH / BK; ++it) {
        const int s = it & 1;
        if (it + 1 < CHH / BK) K5_LOAD(s ^ 1, (it + 1) * BK);
        asm volatile("cp.async.commit_group;");
        asm volatile("cp.async.wait_group 1;");
        __syncthreads();

        const __nv_bfloat16* AB = sm[s][0];
        const __nv_bfloat16* AS = sm[s][1];
        const __nv_bfloat16* BBv = sm[s][2];
        const __nv_bfloat16* BSv = sm[s][3];

        unsigned aB[4][4], aS[4][4], bB[2][4], bS[2][4];
#pragma unroll
        for (int mi = 0; mi < 4; ++mi) {
            ldsm4(aB[mi], &AB[(wm + mi * 16 + arow) * K2P + akof]);
            ldsm4(aS[mi], &AS[(wm + mi * 16 + arow) * K2P + akof]);
        }
#pragma unroll
        for (int nb = 0; nb < 2; ++nb) {
            ldsm4(bB[nb], &BBv[(wn + nb * 16 + brow) * K2P + bkof]);
            ldsm4(bS[nb], &BSv[(wn + nb * 16 + brow) * K2P + bkof]);
        }
#pragma unroll
        for (int mi = 0; mi < 4; ++mi)
#pragma unroll
            for (int ni = 0; ni < 4; ++ni) {
                mma_bf16(acc[mi][ni], aB[mi], &bS[ni >> 1][(ni & 1) * 2]);
                mma_bf16(acc[mi][ni], aS[mi], &bB[ni >> 1][(ni & 1) * 2]);
                mma_bf16(acc[mi][ni], aB[mi], &bB[ni >> 1][(ni & 1) * 2]);
            }
        __syncthreads();
    }

    // epilogue: + Wb + x residual, write fp32 out[b][o][n]
#pragma unroll
    for (int mi = 0; mi < 4; ++mi) {
        int o  = o0 + wm + mi * 16 + g;
        float bb0 = Wb[o], bb1 = Wb[o + 8];
        const float* xr0 = x + (size_t)b * CC * NN + (size_t)o * NN;
        const float* xr1 = xr0 + (size_t)8 * NN;
        float* yr0 = out + (size_t)b * CC * NN + (size_t)o * NN;
        float* yr1 = yr0 + (size_t)8 * NN;
#pragma unroll
        for (int ni = 0; ni < 4; ++ni) {
            int n = n0 + wn + ni * 8 + t * 2;
            float2 x0 = *(const float2*)&xr0[n];
            float2 x1 = *(const float2*)&xr1[n];
            *(float2*)&yr0[n] = make_float2(acc[mi][ni][0] + bb0 + x0.x,
                                            acc[mi][ni][1] + bb0 + x0.y);
            *(float2*)&yr1[n] = make_float2(acc[mi][ni][2] + bb1 + x1.x,
                                            acc[mi][ni][3] + bb1 + x1.y);
        }
    }
}

// ================= launch =================
extern "C" void kernel_launch(void* const* d_in, const int* in_sizes, int n_in,
                              void* d_out, int out_size) {
    const float* x  = (const float*)d_in[0];
    const float* tw = (const float*)d_in[1];
    const float* tb = (const float*)d_in[2];
    const float* pw = (const float*)d_in[3];
    const float* pb = (const float*)d_in[4];
    const float* gw = (const float*)d_in[5];
    const float* gb = (const float*)d_in[6];
    const float* Ww = (const float*)d_in[7];
    const float* Wb = (const float*)d_in[8];
    float* out = (float*)d_out;

    k0_init      <<<dim3(BB * NN / 256),              256>>>();
    k0x_split    <<<dim3(BB * CC * NN / 4 / 256),     256>>>(x);
    k0w_split    <<<dim3(4 * CC * CHH / 256),         256>>>(tw, pw, gw, Ww);
    k1_mma       <<<dim3(NN / 64, 3, BB),             256>>>(tb, pb, gb);
    k2_scores_mma<<<dim3(NN / 128, NN / 128, BB),     256>>>();
    k3_softmax   <<<dim3(BB * NN / 8),                256>>>();
    k4_av_fp16   <<<dim3(NN / 64, BB),                256>>>();
    k5_mma       <<<dim3(NN / 128, CC / 128, BB),     256>>>(x, Wb, out);
}

// round 10
// speedup vs baseline: 1.1887x; 1.0834x over previous
#include <cuda_runtime.h>
#include <cuda_bf16.h>
#include <cuda_fp16.h>

#define BB   4
#define CC   256
#define CHH  128
#define NN   4096

#define BK   16
#define SK   4            // k4 split-K factor
#define JCH  (NN / SK)    // 1024 j per split

// ---------------- scratch ----------------
__device__ float    g_gv   [(size_t)BB * NN * CHH];   // g fp32 (k1 out, k3 in)
__device__ __half   g_gvh  [(size_t)BB * NN * CHH];   // g/Z fp16 (k3 out, k4 in)
__device__ float    g_S    [(size_t)BB * NN * NN];    // scores fp32 [b][j][i]
__device__ __half   g_P    [(size_t)BB * NN * NN];    // probs fp16 [b][j][i]
__device__ unsigned g_rowmax[BB * NN];
__device__ float    g_O4   [(size_t)SK * BB * NN * CHH];  // k4 split-K partials
// attention output as split bf16 (k4r out, k5 in)
__device__ __nv_bfloat16 g_OB [(size_t)BB * NN * CHH];
__device__ __nv_bfloat16 g_OS [(size_t)BB * NN * CHH];
// split-bf16 theta/phi (big + residual)
__device__ __nv_bfloat16 g_thB[(size_t)BB * NN * CHH];
__device__ __nv_bfloat16 g_thS[(size_t)BB * NN * CHH];
__device__ __nv_bfloat16 g_phB[(size_t)BB * NN * CHH];
__device__ __nv_bfloat16 g_phS[(size_t)BB * NN * CHH];
// split-bf16 x, transposed proj weights, and Ww
__device__ __nv_bfloat16 g_xB [(size_t)BB * CC * NN];
__device__ __nv_bfloat16 g_xS [(size_t)BB * CC * NN];
__device__ __nv_bfloat16 g_wTB[3 * CC * CHH];          // [proj][c][o]
__device__ __nv_bfloat16 g_wTS[3 * CC * CHH];
__device__ __nv_bfloat16 g_WoB[CC * CHH];              // Ww [o][c]
__device__ __nv_bfloat16 g_WoS[CC * CHH];

// ---------------- fast exp (FFMA-only, x <= ~0) ----------------
__device__ __forceinline__ float fast_exp(float x) {
    float t = fmaxf(x * 1.4426950408889634f, -120.0f);
    float z = t + 12582912.0f;
    int   e = __float_as_int(z);
    float f = t - (z - 12582912.0f);
    float p = 1.3333558e-3f;
    p = fmaf(p, f, 9.6181291e-3f);
    p = fmaf(p, f, 5.5504109e-2f);
    p = fmaf(p, f, 2.4022651e-1f);
    p = fmaf(p, f, 6.9314718e-1f);
    p = fmaf(p, f, 1.0f);
    return __int_as_float((e << 23) + __float_as_int(p));
}

// ---------------- monotonic float<->uint for atomicMax ----------------
__device__ __forceinline__ unsigned enc_f(float v) {
    unsigned b = __float_as_uint(v);
    return (b & 0x80000000u) ? ~b : (b | 0x80000000u);
}
__device__ __forceinline__ float dec_f(unsigned u) {
    return (u & 0x80000000u) ? __uint_as_float(u & 0x7fffffffu)
                             : __uint_as_float(~u);
}

// ---------------- tensor-core helpers ----------------
__device__ __forceinline__ void mma_bf16(float* d, const unsigned* a, const unsigned* b) {
    asm volatile("mma.sync.aligned.m16n8k16.row.col.f32.bf16.bf16.f32 "
                 "{%0,%1,%2,%3}, {%4,%5,%6,%7}, {%8,%9}, {%0,%1,%2,%3};"
                 : "+f"(d[0]), "+f"(d[1]), "+f"(d[2]), "+f"(d[3])
                 : "r"(a[0]), "r"(a[1]), "r"(a[2]), "r"(a[3]),
                   "r"(b[0]), "r"(b[1]));
}
__device__ __forceinline__ void mma_fp16(float* d, const unsigned* a, const unsigned* b) {
    asm volatile("mma.sync.aligned.m16n8k16.row.col.f32.f16.f16.f32 "
                 "{%0,%1,%2,%3}, {%4,%5,%6,%7}, {%8,%9}, {%0,%1,%2,%3};"
                 : "+f"(d[0]), "+f"(d[1]), "+f"(d[2]), "+f"(d[3])
                 : "r"(a[0]), "r"(a[1]), "r"(a[2]), "r"(a[3]),
                   "r"(b[0]), "r"(b[1]));
}
__device__ __forceinline__ void ldsm4t(unsigned* r, const void* smem) {
    unsigned a = (unsigned)__cvta_generic_to_shared(smem);
    asm volatile("ldmatrix.sync.aligned.m8n8.x4.trans.shared.b16 {%0,%1,%2,%3}, [%4];"
                 : "=r"(r[0]), "=r"(r[1]), "=r"(r[2]), "=r"(r[3]) : "r"(a));
}
__device__ __forceinline__ void ldsm4(unsigned* r, const void* smem) {
    unsigned a = (unsigned)__cvta_generic_to_shared(smem);
    asm volatile("ldmatrix.sync.aligned.m8n8.x4.shared.b16 {%0,%1,%2,%3}, [%4];"
                 : "=r"(r[0]), "=r"(r[1]), "=r"(r[2]), "=r"(r[3]) : "r"(a));
}
__device__ __forceinline__ void cp16(void* smem, const void* g) {
    unsigned a = (unsigned)__cvta_generic_to_shared(smem);
    asm volatile("cp.async.cg.shared.global [%0], [%1], 16;" :: "r"(a), "l"(g));
}
// split a float2 into packed bf16x2 (big) + packed bf16x2 (residual)
__device__ __forceinline__ void split2(float v0, float v1, unsigned& big, unsigned& sml) {
    asm("cvt.rn.bf16x2.f32 %0, %1, %2;" : "=r"(big) : "f"(v1), "f"(v0));
    float b0 = __uint_as_float(big << 16);
    float b1 = __uint_as_float(big & 0xffff0000u);
    float r0 = v0 - b0, r1 = v1 - b1;
    asm("cvt.rn.bf16x2.f32 %0, %1, %2;" : "=r"(sml) : "f"(r1), "f"(r0));
}

// ================= K0: init rowmax =================
__global__ __launch_bounds__(256) void k0_init() {
    g_rowmax[blockIdx.x * 256 + threadIdx.x] = 0u;
}

// ================= K0x: split x -> bf16 big/small planes =================
__global__ __launch_bounds__(256) void k0x_split(const float* __restrict__ x) {
    size_t i4 = (size_t)blockIdx.x * 256 + threadIdx.x;
    float4 v = ((const float4*)x)[i4];
    unsigned b0, s0, b1, s1;
    split2(v.x, v.y, b0, s0);
    split2(v.z, v.w, b1, s1);
    ((uint2*)g_xB)[i4] = make_uint2(b0, b1);
    ((uint2*)g_xS)[i4] = make_uint2(s0, s1);
}

// ================= K0w: split weights (proj transposed; Ww direct) =================
__global__ __launch_bounds__(256) void k0w_split(
    const float* __restrict__ tw, const float* __restrict__ pw,
    const float* __restrict__ gw, const float* __restrict__ Ww) {
    int idx = blockIdx.x * 256 + threadIdx.x;   // 4*256*128
    if (idx < 3 * CC * CHH) {
        int o = idx & 127;
        int c = (idx >> 7) & 255;
        int p = idx >> 15;
        const float* w = p == 0 ? tw : (p == 1 ? pw : gw);
        float v = w[o * CC + c];
        __nv_bfloat16 big = __float2bfloat16(v);
        g_wTB[idx] = big;
        g_wTS[idx] = __float2bfloat16(v - __bfloat162float(big));
    } else {
        int j = idx - 3 * CC * CHH;
        float v = Ww[j];
        __nv_bfloat16 big = __float2bfloat16(v);
        g_WoB[j] = big;
        g_WoS[j] = __float2bfloat16(v - __bfloat162float(big));
    }
}

// ================= K1: projections via split-bf16 x3 mma =================
#define K1_PA 72
#define K1_PB 136
__global__ __launch_bounds__(256) void k1_mma(
    const float* __restrict__ tb, const float* __restrict__ pb,
    const float* __restrict__ gb)
{
    __shared__ __align__(16) __nv_bfloat16 As[3][2][BK * K1_PA];
    __shared__ __align__(16) __nv_bfloat16 Bs[3][2][BK * K1_PB];
    const int b    = blockIdx.z;
    const int proj = blockIdx.y;
    const int i0   = blockIdx.x * 64;
    const int tid  = threadIdx.x;
    const int warp = tid >> 5, lane = tid & 31;
    const int g = lane >> 2, t = lane & 3;
    const int wm = (warp >> 2) * 32;
    const int wn = (warp & 3) * 32;

    const __nv_bfloat16* xB = g_xB + (size_t)b * CC * NN;
    const __nv_bfloat16* xS = g_xS + (size_t)b * CC * NN;
    const __nv_bfloat16* wB = g_wTB + (size_t)proj * CC * CHH;
    const __nv_bfloat16* wS = g_wTS + (size_t)proj * CC * CHH;
    const float* bias = proj == 0 ? tb : (proj == 1 ? pb : gb);

    const int krA = (lane & 7) + ((lane & 16) ? 8 : 0);
    const int mcA = (lane & 8) ? 8 : 0;
    const int krB = (lane & 7) + ((lane & 8) ? 8 : 0);
    const int ncB = (lane & 16) ? 8 : 0;

    const int av  = tid >> 7, ac = tid & 127;
    const int ar  = ac >> 3, acol = (ac & 7) * 8;
    float acc[2][4][4] = {};

#define K1_LOAD(st, k0)                                                              \
    {                                                                                \
        const __nv_bfloat16* xa = av ? xS : xB;                                      \
        cp16(&As[st][av][ar * K1_PA + acol],                                         \
             xa + (size_t)((k0) + ar) * NN + i0 + acol);                             \
        _Pragma("unroll")                                                            \
        for (int q = 0; q < 2; ++q) {                                                \
            int idx = tid + q * 256;                                                 \
            int bv = idx >> 8, cc = idx & 255;                                       \
            int br = cc >> 4, bcol = (cc & 15) * 8;                                  \
            const __nv_bfloat16* wa = bv ? wS : wB;                                  \
            cp16(&Bs[st][bv][br * K1_PB + bcol],                                     \
                 wa + (size_t)((k0) + br) * CHH + bcol);                             \
        }                                                                            \
    }

    K1_LOAD(0, 0);
    asm volatile("cp.async.commit_group;");
    K1_LOAD(1, BK);
    asm volatile("cp.async.commit_group;");

    int s = 0;
#pragma unroll 1
    for (int it = 0; it < CC / BK; ++it) {
        asm volatile("cp.async.wait_group 1;");
        __syncthreads();

        if (it + 2 < CC / BK) {
            int st = s + 2; if (st >= 3) st -= 3;
            K1_LOAD(st, (it + 2) * BK);
        }
        asm volatile("cp.async.commit_group;");

        unsigned aB[2][4], aS[2][4], bB[2][4], bS[2][4];
#pragma unroll
        for (int mi = 0; mi < 2; ++mi) {
            ldsm4t(aB[mi], &As[s][0][krA * K1_PA + wm + mi * 16 + mcA]);
            ldsm4t(aS[mi], &As[s][1][krA * K1_PA + wm + mi * 16 + mcA]);
        }
#pragma unroll
        for (int nb = 0; nb < 2; ++nb) {
            ldsm4t(bB[nb], &Bs[s][0][krB * K1_PB + wn + nb * 16 + ncB]);
            ldsm4t(bS[nb], &Bs[s][1][krB * K1_PB + wn + nb * 16 + ncB]);
        }
#pragma unroll
        for (int mi = 0; mi < 2; ++mi)
#pragma unroll
            for (int ni = 0; ni < 4; ++ni) {
                mma_bf16(acc[mi][ni], aB[mi], &bS[ni >> 1][(ni & 1) * 2]);
                mma_bf16(acc[mi][ni], aS[mi], &bB[ni >> 1][(ni & 1) * 2]);
                mma_bf16(acc[mi][ni], aB[mi], &bB[ni >> 1][(ni & 1) * 2]);
            }
        __syncthreads();
        if (++s == 3) s = 0;
    }

    if (proj < 2) {
        __nv_bfloat16* outB = proj == 0 ? g_thB : g_phB;
        __nv_bfloat16* outS = proj == 0 ? g_thS : g_phS;
        size_t base = (size_t)b * NN * CHH;
#pragma unroll
        for (int mi = 0; mi < 2; ++mi) {
            int i = i0 + wm + mi * 16 + g;
#pragma unroll
            for (int ni = 0; ni < 4; ++ni) {
                int o = wn + ni * 8 + t * 2;
                float b0 = bias[o], b1 = bias[o + 1];
                unsigned pbv, psv;
                split2(acc[mi][ni][0] + b0, acc[mi][ni][1] + b1, pbv, psv);
                *(unsigned*)&outB[base + (size_t)i * CHH + o] = pbv;
                *(unsigned*)&outS[base + (size_t)i * CHH + o] = psv;
                split2(acc[mi][ni][2] + b0, acc[mi][ni][3] + b1, pbv, psv);
                *(unsigned*)&outB[base + (size_t)(i + 8) * CHH + o] = pbv;
                *(unsigned*)&outS[base + (size_t)(i + 8) * CHH + o] = psv;
            }
        }
    } else {
        float* ob = g_gv + (size_t)b * NN * CHH;
#pragma unroll
        for (int mi = 0; mi < 2; ++mi) {
            int i = i0 + wm + mi * 16 + g;
#pragma unroll
            for (int ni = 0; ni < 4; ++ni) {
                int o = wn + ni * 8 + t * 2;
                float b0 = bias[o], b1 = bias[o + 1];
                *(float2*)&ob[(size_t)i * CHH + o] =
                    make_float2(acc[mi][ni][0] + b0, acc[mi][ni][1] + b1);
                *(float2*)&ob[(size_t)(i + 8) * CHH + o] =
                    make_float2(acc[mi][ni][2] + b0, acc[mi][ni][3] + b1);
            }
        }
    }
}

// ================= K2: S = theta.phi^T (split-bf16 x3, 3-stage, 1 sync/iter) =====
// dynamic smem: 3 stages x {thB, thS, phB, phS} x 128 x K2P bf16
#define K2P 24
#define K2_STAGE_ELEMS (4 * 128 * K2P)
#define K2_SMEM_BYTES  (3 * K2_STAGE_ELEMS * 2)
__global__ __launch_bounds__(256) void k2_scores_mma()
{
    extern __shared__ __align__(16) __nv_bfloat16 smc[];
    const int b  = blockIdx.z;
    const int j0 = blockIdx.y * 128;
    const int i0 = blockIdx.x * 128;
    const int tid = threadIdx.x;
    const int warp = tid >> 5, lane = tid & 31;
    const int g = lane >> 2, t = lane & 3;
    const int wm = (warp >> 2) * 64;
    const int wn = (warp & 3) * 32;
    const size_t baseJ = (size_t)b * NN * CHH + (size_t)j0 * CHH;
    const size_t baseI = (size_t)b * NN * CHH + (size_t)i0 * CHH;
    const __nv_bfloat16* thB = g_thB + baseJ;
    const __nv_bfloat16* thS = g_thS + baseJ;
    const __nv_bfloat16* phB = g_phB + baseI;
    const __nv_bfloat16* phS = g_phS + baseI;

    const int arow = (lane & 7) + ((lane & 8) ? 8 : 0);
    const int akof = (lane & 16) ? 8 : 0;
    const int brow = (lane & 7) + ((lane & 16) ? 8 : 0);
    const int bkof = (lane & 8) ? 8 : 0;

    float acc[4][4][4] = {};

    const int lrow = tid >> 1, lkc = (tid & 1) * 8;
#define K2SM(st, op) (smc + ((st) * 4 + (op)) * (128 * K2P))
#define K2_LOAD(st, k0)                                                            \
    {                                                                              \
        cp16(K2SM(st, 0) + lrow * K2P + lkc, thB + (size_t)lrow * CHH + (k0) + lkc); \
        cp16(K2SM(st, 1) + lrow * K2P + lkc, thS + (size_t)lrow * CHH + (k0) + lkc); \
        cp16(K2SM(st, 2) + lrow * K2P + lkc, phB + (size_t)lrow * CHH + (k0) + lkc); \
        cp16(K2SM(st, 3) + lrow * K2P + lkc, phS + (size_t)lrow * CHH + (k0) + lkc); \
    }

    K2_LOAD(0, 0);
    asm volatile("cp.async.commit_group;");
    K2_LOAD(1, BK);
    asm volatile("cp.async.commit_group;");

    int s = 0;
#pragma unroll 1
    for (int it = 0; it < CHH / BK; ++it) {
        asm volatile("cp.async.wait_group 1;");
        __syncthreads();

        if (it + 2 < CHH / BK) {
            int st = s + 2; if (st >= 3) st -= 3;
            K2_LOAD(st, (it + 2) * BK);
        }
        asm volatile("cp.async.commit_group;");

        const __nv_bfloat16* AB = K2SM(s, 0);
        const __nv_bfloat16* AS = K2SM(s, 1);
        const __nv_bfloat16* PBp = K2SM(s, 2);
        const __nv_bfloat16* PSp = K2SM(s, 3);

        unsigned aB[4][4], aS[4][4], bB[2][4], bS[2][4];
#pragma unroll
        for (int mi = 0; mi < 4; ++mi) {
            ldsm4(aB[mi], &AB[(wm + mi * 16 + arow) * K2P + akof]);
            ldsm4(aS[mi], &AS[(wm + mi * 16 + arow) * K2P + akof]);
        }
#pragma unroll
        for (int nb = 0; nb < 2; ++nb) {
            ldsm4(bB[nb], &PBp[(wn + nb * 16 + brow) * K2P + bkof]);
            ldsm4(bS[nb], &PSp[(wn + nb * 16 + brow) * K2P + bkof]);
        }
#pragma unroll
        for (int mi = 0; mi < 4; ++mi)
#pragma unroll
            for (int ni = 0; ni < 4; ++ni) {
                mma_bf16(acc[mi][ni], aB[mi], &bS[ni >> 1][(ni & 1) * 2]);
                mma_bf16(acc[mi][ni], aS[mi], &bB[ni >> 1][(ni & 1) * 2]);
                mma_bf16(acc[mi][ni], aB[mi], &bB[ni >> 1][(ni & 1) * 2]);
            }
        if (++s == 3) s = 0;
    }

    float* Sb = g_S + (size_t)b * NN * NN;
#pragma unroll
    for (int mi = 0; mi < 4; ++mi) {
        int j = j0 + wm + mi * 16 + g;
        float r0 = -3.0e38f, r1 = -3.0e38f;
#pragma unroll
        for (int ni = 0; ni < 4; ++ni) {
            int i = i0 + wn + ni * 8 + t * 2;
            *(float2*)&Sb[(size_t)j * NN + i] =
                make_float2(acc[mi][ni][0], acc[mi][ni][1]);
            *(float2*)&Sb[(size_t)(j + 8) * NN + i] =
                make_float2(acc[mi][ni][2], acc[mi][ni][3]);
            r0 = fmaxf(r0, fmaxf(acc[mi][ni][0], acc[mi][ni][1]));
            r1 = fmaxf(r1, fmaxf(acc[mi][ni][2], acc[mi][ni][3]));
        }
        r0 = fmaxf(r0, __shfl_xor_sync(0xffffffffu, r0, 1));
        r0 = fmaxf(r0, __shfl_xor_sync(0xffffffffu, r0, 2));
        r1 = fmaxf(r1, __shfl_xor_sync(0xffffffffu, r1, 1));
        r1 = fmaxf(r1, __shfl_xor_sync(0xffffffffu, r1, 2));
        if (t == 0) {
            atomicMax(&g_rowmax[b * NN + j],     enc_f(r0));
            atomicMax(&g_rowmax[b * NN + j + 8], enc_f(r1));
        }
    }
}

// ================= K3: read S fp32, write P fp16; fold 1/Z into g (fp16) =========
__global__ __launch_bounds__(256) void k3_softmax()
{
    const int warp = threadIdx.x >> 5, lane = threadIdx.x & 31;
    const size_t row = (size_t)blockIdx.x * 8 + warp;
    const float mx = dec_f(g_rowmax[row]);
    const float4* S4 = (const float4*)(g_S + row * NN);
    uint2* P2 = (uint2*)(g_P + row * NN);

    float s = 0.f;
#pragma unroll 4
    for (int it = lane; it < NN / 4; it += 32) {
        float4 v = S4[it];
        v.x = fast_exp(v.x - mx);
        v.y = fast_exp(v.y - mx);
        v.z = fast_exp(v.z - mx);
        v.w = fast_exp(v.w - mx);
        s += (v.x + v.y) + (v.z + v.w);
        __half2 h0 = __floats2half2_rn(v.x, v.y);
        __half2 h1 = __floats2half2_rn(v.z, v.w);
        P2[it] = make_uint2(*(unsigned*)&h0, *(unsigned*)&h1);
    }
#pragma unroll
    for (int o = 16; o; o >>= 1) s += __shfl_xor_sync(0xffffffffu, s, o);
    const float z = 1.0f / s;

    const float4* gv4 = (const float4*)(g_gv + row * CHH);
    uint2* gh2 = (uint2*)(g_gvh + row * CHH);
    float4 v = gv4[lane];
    __half2 h0 = __floats2half2_rn(v.x * z, v.y * z);
    __half2 h1 = __floats2half2_rn(v.z * z, v.w * z);
    gh2[lane] = make_uint2(*(unsigned*)&h0, *(unsigned*)&h1);
}

// ================= K4: split-K fp16 mma; partials fp32 -> g_O4 ====================
#define K4BK  32
#define K4_PA 72
#define K4_PB 136
__global__ __launch_bounds__(256) void k4_av_fp16()
{
    __shared__ __align__(16) __half As[3][K4BK * K4_PA];
    __shared__ __align__(16) __half Bs[3][K4BK * K4_PB];
    const int b  = blockIdx.z;
    const int sk = blockIdx.y;
    const int i0 = blockIdx.x * 64;
    const int jb = sk * JCH;
    const int tid = threadIdx.x;
    const int warp = tid >> 5, lane = tid & 31;
    const int g = lane >> 2, t = lane & 3;
    const int wm = (warp >> 2) * 32;
    const int wn = (warp & 3) * 32;
    const __half* Pb = g_P   + (size_t)b * NN * NN;
    const __half* gh = g_gvh + (size_t)b * NN * CHH;

    const int krA = (lane & 7) + ((lane & 16) ? 8 : 0);
    const int mcA = (lane & 8) ? 8 : 0;
    const int krB = (lane & 7) + ((lane & 8) ? 8 : 0);
    const int ncB = (lane & 16) ? 8 : 0;

    const int arow = tid >> 3, acol = (tid & 7) * 8;
    const int brow0 = tid >> 4, bcol = (tid & 15) * 8;
    const int brow1 = brow0 + 16;

    float acc[2][4][4] = {};

#define K4_LOAD(st, j0)                                                          \
    {                                                                            \
        cp16(&As[st][arow * K4_PA + acol],  Pb + (size_t)((j0) + arow) * NN + i0 + acol); \
        cp16(&Bs[st][brow0 * K4_PB + bcol], gh + (size_t)((j0) + brow0) * CHH + bcol);    \
        cp16(&Bs[st][brow1 * K4_PB + bcol], gh + (size_t)((j0) + brow1) * CHH + bcol);    \
    }

    K4_LOAD(0, jb);
    asm volatile("cp.async.commit_group;");
    K4_LOAD(1, jb + K4BK);
    asm volatile("cp.async.commit_group;");

    int s = 0;
#pragma unroll 1
    for (int it = 0; it < JCH / K4BK; ++it) {
        asm volatile("cp.async.wait_group 1;");
        __syncthreads();

        if (it + 2 < JCH / K4BK) {
            int st = s + 2; if (st >= 3) st -= 3;
            K4_LOAD(st, jb + (it + 2) * K4BK);
        }
        asm volatile("cp.async.commit_group;");

#pragma unroll
        for (int ks = 0; ks < K4BK; ks += 16) {
            unsigned a[2][4], bq[2][4];
#pragma unroll
            for (int mi = 0; mi < 2; ++mi)
                ldsm4t(a[mi], &As[s][(ks + krA) * K4_PA + wm + mi * 16 + mcA]);
#pragma unroll
            for (int nb = 0; nb < 2; ++nb)
                ldsm4t(bq[nb], &Bs[s][(ks + krB) * K4_PB + wn + nb * 16 + ncB]);
#pragma unroll
            for (int mi = 0; mi < 2; ++mi)
#pragma unroll
                for (int ni = 0; ni < 4; ++ni)
                    mma_fp16(acc[mi][ni], a[mi], &bq[ni >> 1][(ni & 1) * 2]);
        }
        __syncthreads();
        if (++s == 3) s = 0;
    }

    float* Op = g_O4 + ((size_t)sk * BB + b) * NN * CHH;
#pragma unroll
    for (int mi = 0; mi < 2; ++mi)
#pragma unroll
        for (int ni = 0; ni < 4; ++ni) {
            int i = i0 + wm + mi * 16 + g;
            int c = wn + ni * 8 + t * 2;
            *(float2*)&Op[(size_t)i * CHH + c] =
                make_float2(acc[mi][ni][0], acc[mi][ni][1]);
            *(float2*)&Op[(size_t)(i + 8) * CHH + c] =
                make_float2(acc[mi][ni][2], acc[mi][ni][3]);
        }
}

// ================= K4r: reduce split-K partials -> split-bf16 O ===================
__global__ __launch_bounds__(256) void k4r_reduce()
{
    size_t p = (size_t)blockIdx.x * 256 + threadIdx.x;   // pair index
    const float2* O0 = (const float2*)(g_O4 + (size_t)0 * BB * NN * CHH);
    const float2* O1 = (const float2*)(g_O4 + (size_t)1 * BB * NN * CHH);
    const float2* O2 = (const float2*)(g_O4 + (size_t)2 * BB * NN * CHH);
    const float2* O3 = (const float2*)(g_O4 + (size_t)3 * BB * NN * CHH);
    float2 a = O0[p], b = O1[p], c = O2[p], d = O3[p];
    float v0 = (a.x + b.x) + (c.x + d.x);
    float v1 = (a.y + b.y) + (c.y + d.y);
    unsigned pb, ps;
    split2(v0, v1, pb, ps);
    ((unsigned*)g_OB)[p] = pb;
    ((unsigned*)g_OS)[p] = ps;
}

// ================= K5: out = Ww.O + Wb + x  (split-bf16 x3 mma) ==================
__global__ __launch_bounds__(256) void k5_mma(
    const float* __restrict__ x, const float* __restrict__ Wb,
    float* __restrict__ out)
{
    __shared__ __align__(16) __nv_bfloat16 sm[2][4][128 * K2P];
    const int b  = blockIdx.z;
    const int o0 = blockIdx.y * 128;
    const int n0 = blockIdx.x * 128;
    const int tid = threadIdx.x;
    const int warp = tid >> 5, lane = tid & 31;
    const int g = lane >> 2, t = lane & 3;
    const int wm = (warp >> 2) * 64;
    const int wn = (warp & 3) * 32;
    const __nv_bfloat16* WoB = g_WoB + (size_t)o0 * CHH;
    const __nv_bfloat16* WoS = g_WoS + (size_t)o0 * CHH;
    const __nv_bfloat16* OB  = g_OB + (size_t)b * NN * CHH + (size_t)n0 * CHH;
    const __nv_bfloat16* OS  = g_OS + (size_t)b * NN * CHH + (size_t)n0 * CHH;

    const int arow = (lane & 7) + ((lane & 8) ? 8 : 0);
    const int akof = (lane & 16) ? 8 : 0;
    const int brow = (lane & 7) + ((lane & 16) ? 8 : 0);
    const int bkof = (lane & 8) ? 8 : 0;

    float acc[4][4][4] = {};

    const int lrow = tid >> 1, lkc = (tid & 1) * 8;
#define K5_LOAD(st, k0)                                                        \
    {                                                                          \
        cp16(&sm[st][0][lrow * K2P + lkc], WoB + (size_t)lrow * CHH + (k0) + lkc); \
        cp16(&sm[st][1][lrow * K2P + lkc], WoS + (size_t)lrow * CHH + (k0) + lkc); \
        cp16(&sm[st][2][lrow * K2P + lkc], OB  + (size_t)lrow * CHH + (k0) + lkc); \
        cp16(&sm[st][3][lrow * K2P + lkc], OS  + (size_t)lrow * CHH + (k0) + lkc); \
    }

    K5_LOAD(0, 0);
    asm volatile("cp.async.commit_group;");

#pragma unroll 1
    for (int it = 0; it < CHH / BK; ++it) {
        const int s = it & 1;
        if (it + 1 < CHH / BK) K5_LOAD(s ^ 1, (it + 1) * BK);
        asm volatile("cp.async.commit_group;");
        asm volatile("cp.async.wait_group 1;");
        __syncthreads();

        const __nv_bfloat16* AB = sm[s][0];
        const __nv_bfloat16* AS = sm[s][1];
        const __nv_bfloat16* BBv = sm[s][2];
        const __nv_bfloat16* BSv = sm[s][3];

        unsigned aB[4][4], aS[4][4], bB[2][4], bS[2][4];
#pragma unroll
        for (int mi = 0; mi < 4; ++mi) {
            ldsm4(aB[mi], &AB[(wm + mi * 16 + arow) * K2P + akof]);
            ldsm4(aS[mi], &AS[(wm + mi * 16 + arow) * K2P + akof]);
        }
#pragma unroll
        for (int nb = 0; nb < 2; ++nb) {
            ldsm4(bB[nb], &BBv[(wn + nb * 16 + brow) * K2P + bkof]);
            ldsm4(bS[nb], &BSv[(wn + nb * 16 + brow) * K2P + bkof]);
        }
#pragma unroll
        for (int mi = 0; mi < 4; ++mi)
#pragma unroll
            for (int ni = 0; ni < 4; ++ni) {
                mma_bf16(acc[mi][ni], aB[mi], &bS[ni >> 1][(ni & 1) * 2]);
                mma_bf16(acc[mi][ni], aS[mi], &bB[ni >> 1][(ni & 1) * 2]);
                mma_bf16(acc[mi][ni], aB[mi], &bB[ni >> 1][(ni & 1) * 2]);
            }
        __syncthreads();
    }

#pragma unroll
    for (int mi = 0; mi < 4; ++mi) {
        int o  = o0 + wm + mi * 16 + g;
        float bb0 = Wb[o], bb1 = Wb[o + 8];
        const float* xr0 = x + (size_t)b * CC * NN + (size_t)o * NN;
        const float* xr1 = xr0 + (size_t)8 * NN;
        float* yr0 = out + (size_t)b * CC * NN + (size_t)o * NN;
        float* yr1 = yr0 + (size_t)8 * NN;
#pragma unroll
        for (int ni = 0; ni < 4; ++ni) {
            int n = n0 + wn + ni * 8 + t * 2;
            float2 x0 = *(const float2*)&xr0[n];
            float2 x1 = *(const float2*)&xr1[n];
            *(float2*)&yr0[n] = make_float2(acc[mi][ni][0] + bb0 + x0.x,
                                            acc[mi][ni][1] + bb0 + x0.y);
            *(float2*)&yr1[n] = make_float2(acc[mi][ni][2] + bb1 + x1.x,
                                            acc[mi][ni][3] + bb1 + x1.y);
        }
    }
}

// ================= launch =================
extern "C" void kernel_launch(void* const* d_in, const int* in_sizes, int n_in,
                              void* d_out, int out_size) {
    const float* x  = (const float*)d_in[0];
    const float* tw = (const float*)d_in[1];
    const float* tb = (const float*)d_in[2];
    const float* pw = (const float*)d_in[3];
    const float* pb = (const float*)d_in[4];
    const float* gw = (const float*)d_in[5];
    const float* gb = (const float*)d_in[6];
    const float* Ww = (const float*)d_in[7];
    const float* Wb = (const float*)d_in[8];
    float* out = (float*)d_out;

    cudaFuncSetAttribute(k2_scores_mma,
                         cudaFuncAttributeMaxDynamicSharedMemorySize, K2_SMEM_BYTES);

    k0_init      <<<dim3(BB * NN / 256),                 256>>>();
    k0x_split    <<<dim3(BB * CC * NN / 4 / 256),        256>>>(x);
    k0w_split    <<<dim3(4 * CC * CHH / 256),            256>>>(tw, pw, gw, Ww);
    k1_mma       <<<dim3(NN / 64, 3, BB),                256>>>(tb, pb, gb);
    k2_scores_mma<<<dim3(NN / 128, NN / 128, BB), 256, K2_SMEM_BYTES>>>();
    k3_softmax   <<<dim3(BB * NN / 8),                   256>>>();
    k4_av_fp16   <<<dim3(NN / 64, SK, BB),               256>>>();
    k4r_reduce   <<<dim3(BB * NN * CHH / 2 / 256),       256>>>();
    k5_mma       <<<dim3(NN / 128, CC / 128, BB),        256>>>(x, Wb, out);
}